// round 16
// baseline (speedup 1.0000x reference)
#include <cuda_runtime.h>
#include <cuda_fp16.h>

#define N_NODES 100000
#define N_EDGES 1600000
#define N_FEAT  256
#define N_HID   64
#define N_CLS   16

#define SCAN_BLK  512
#define SCAN_NBLK ((N_NODES + SCAN_BLK - 1) / SCAN_BLK)   // 196

// ---------------- scratch (device globals: allocation-free, graph-safe) ----
__device__ __half2 g_h0h[N_NODES * (N_HID / 2)];  // x@W1+b1, fp16 pairs
__device__ __half2 g_hh [N_NODES * (N_HID / 2)];  // relu(spmm1), fp16 pairs
__device__ __half  g_h2h[N_NODES * N_CLS];        // h@W2+b2, fp16
__device__ int     g_cnt[N_NODES];
__device__ int     g_scan[N_NODES];
__device__ int     g_blk[SCAN_NBLK];
__device__ int     g_ptr[N_NODES + 1];
__device__ int     g_cur[N_NODES];
__device__ int2    g_edge[N_EDGES];               // {col, float_bits(val)} by row

// ---------------------------------------------------------------------------
// CSR build — 4 edges per thread (vectorized loads, 4 independent
// atomic chains for latency overlap). 1.6M % 4 == 0: no tail.
// ---------------------------------------------------------------------------
__global__ void k_hist(const int* __restrict__ row) {
    int i = blockIdx.x * blockDim.x + threadIdx.x;
    int e = i * 4;
    if (e >= N_EDGES) return;
    int4 r4 = *(const int4*)(row + e);
    atomicAdd(&g_cnt[r4.x], 1);
    atomicAdd(&g_cnt[r4.y], 1);
    atomicAdd(&g_cnt[r4.z], 1);
    atomicAdd(&g_cnt[r4.w], 1);
}

__global__ __launch_bounds__(SCAN_BLK) void k_scan1() {
    __shared__ int s[SCAN_BLK];
    int i = blockIdx.x * SCAN_BLK + threadIdx.x;
    int v = (i < N_NODES) ? g_cnt[i] : 0;
    s[threadIdx.x] = v;
    __syncthreads();
    for (int off = 1; off < SCAN_BLK; off <<= 1) {
        int t = (threadIdx.x >= off) ? s[threadIdx.x - off] : 0;
        __syncthreads();
        s[threadIdx.x] += t;
        __syncthreads();
    }
    if (i < N_NODES) g_scan[i] = s[threadIdx.x];
    if (threadIdx.x == SCAN_BLK - 1) g_blk[blockIdx.x] = s[threadIdx.x];
}

__global__ __launch_bounds__(SCAN_BLK) void k_scan3() {
    __shared__ int s[SCAN_BLK];
    int t = threadIdx.x;
    s[t] = (t < SCAN_NBLK && t < (int)blockIdx.x) ? g_blk[t] : 0;
    __syncthreads();
    for (int off = SCAN_BLK / 2; off; off >>= 1) {
        if (t < off) s[t] += s[t + off];
        __syncthreads();
    }
    int blkoff = s[0];
    int i = blockIdx.x * SCAN_BLK + t;
    if (i < N_NODES) {
        int excl = g_scan[i] - g_cnt[i] + blkoff;
        g_ptr[i] = excl;
        g_cur[i] = excl;
    }
    if (i == 0) g_ptr[N_NODES] = N_EDGES;
}

__global__ void k_scatter(const int* __restrict__ row, const int* __restrict__ col,
                          const float* __restrict__ vals) {
    int i = blockIdx.x * blockDim.x + threadIdx.x;
    int e = i * 4;
    if (e >= N_EDGES) return;
    int4   r4 = *(const int4*)(row + e);
    int4   c4 = *(const int4*)(col + e);
    float4 v4 = *(const float4*)(vals + e);
    int p0 = atomicAdd(&g_cur[r4.x], 1);
    int p1 = atomicAdd(&g_cur[r4.y], 1);
    int p2 = atomicAdd(&g_cur[r4.z], 1);
    int p3 = atomicAdd(&g_cur[r4.w], 1);
    g_edge[p0] = make_int2(c4.x, __float_as_int(v4.x));
    g_edge[p1] = make_int2(c4.y, __float_as_int(v4.y));
    g_edge[p2] = make_int2(c4.z, __float_as_int(v4.z));
    g_edge[p3] = make_int2(c4.w, __float_as_int(v4.w));
}

// ---------------------------------------------------------------------------
// mma + cp.async helpers
// ---------------------------------------------------------------------------
__device__ __forceinline__ void mma_tf32(float c[4], unsigned a0, unsigned a1,
                                         unsigned a2, unsigned a3,
                                         unsigned b0, unsigned b1) {
    asm("mma.sync.aligned.m16n8k8.row.col.f32.tf32.tf32.f32 "
        "{%0,%1,%2,%3}, {%4,%5,%6,%7}, {%8,%9}, {%0,%1,%2,%3};"
        : "+f"(c[0]), "+f"(c[1]), "+f"(c[2]), "+f"(c[3])
        : "r"(a0), "r"(a1), "r"(a2), "r"(a3), "r"(b0), "r"(b1));
}

__device__ __forceinline__ void cp16(unsigned* dst_smem, const void* src, bool pred) {
    unsigned saddr = (unsigned)__cvta_generic_to_shared(dst_smem);
    int sz = pred ? 16 : 0;
    asm volatile("cp.async.cg.shared.global [%0], [%1], 16, %2;\n"
                 :: "r"(saddr), "l"(src), "r"(sz));
}
__device__ __forceinline__ void cp_commit() {
    asm volatile("cp.async.commit_group;\n");
}
__device__ __forceinline__ void cp_wait_all() {
    asm volatile("cp.async.wait_group 0;\n");
}

// ---------------------------------------------------------------------------
// GEMM1 (tf32 tensor cores, cp.async 2-stage, KT=16) — proven R12 version.
// ---------------------------------------------------------------------------
__global__ __launch_bounds__(256) void k_gemm1(const float* __restrict__ x,
                                               const float* __restrict__ W1,
                                               const float* __restrict__ b1) {
    __shared__ unsigned xs[2][128][20];
    __shared__ unsigned ws[2][16][72];
    __shared__ float b1s[64];

    int tid = threadIdx.x;
    int n0 = blockIdx.x * 128;
    if (tid < 64) b1s[tid] = b1[tid];

    int warp = tid >> 5, lane = tid & 31;
    int qr = lane >> 2, qc = lane & 3;

    int xr = tid >> 1, xc = (tid & 1) * 8;
    long gn = n0 + xr;
    bool xok = (gn < N_NODES);
    const float* xsrc = x + (xok ? gn : 0) * N_FEAT + xc;
    int wk = tid >> 4, wc = (tid & 15) * 4;

    {
        unsigned* xd = &xs[0][xr][xc];
        cp16(xd, xsrc, xok);
        cp16(xd + 4, xsrc + 4, xok);
        cp16(&ws[0][wk][wc], W1 + (long)wk * N_HID + wc, true);
        cp_commit();
    }

    float c[8][4];
#pragma unroll
    for (int i = 0; i < 8; i++)
#pragma unroll
        for (int j = 0; j < 4; j++) c[i][j] = 0.0f;

    int m = warp * 16 + qr;

    const int NCHUNK = N_FEAT / 16;
    for (int ch = 0; ch < NCHUNK; ch++) {
        int cur = ch & 1;
        cp_wait_all();
        __syncthreads();

        if (ch + 1 < NCHUNK) {
            int k0 = (ch + 1) * 16;
            int nxt = cur ^ 1;
            unsigned* xd = &xs[nxt][xr][xc];
            cp16(xd, xsrc + k0, xok);
            cp16(xd + 4, xsrc + k0 + 4, xok);
            cp16(&ws[nxt][wk][wc], W1 + (long)(k0 + wk) * N_HID + wc, true);
            cp_commit();
        }

        const unsigned (*X)[20] = xs[cur];
        const unsigned (*W)[72] = ws[cur];
#pragma unroll
        for (int ks = 0; ks < 2; ks++) {
            int kq = ks * 8 + qc;
            unsigned a0 = X[m][kq];
            unsigned a1 = X[m + 8][kq];
            unsigned a2 = X[m][kq + 4];
            unsigned a3 = X[m + 8][kq + 4];
#pragma unroll
            for (int nt = 0; nt < 8; nt++) {
                unsigned b0 = W[kq][nt * 8 + qr];
                unsigned b1v = W[kq + 4][nt * 8 + qr];
                mma_tf32(c[nt], a0, a1, a2, a3, b0, b1v);
            }
        }
    }

    int row0 = n0 + warp * 16 + qr;
    int row1 = row0 + 8;
#pragma unroll
    for (int nt = 0; nt < 8; nt++) {
        int cc = nt * 8 + qc * 2;
        float bb0 = b1s[cc], bb1 = b1s[cc + 1];
        if (row0 < N_NODES)
            g_h0h[(long)row0 * 32 + (cc >> 1)] =
                __floats2half2_rn(c[nt][0] + bb0, c[nt][1] + bb1);
        if (row1 < N_NODES)
            g_h0h[(long)row1 * 32 + (cc >> 1)] =
                __floats2half2_rn(c[nt][2] + bb0, c[nt][3] + bb1);
    }
}

// ---------------------------------------------------------------------------
// SpMM1 gather + ReLU only (low registers -> high occupancy).
// Two rows per warp, interleaved independent chains (proven R14/R15 loop).
// ---------------------------------------------------------------------------
__global__ __launch_bounds__(256) void k_spmm1g() {
    int tid = threadIdx.x;
    int warp = tid >> 5, lane = tid & 31;
    int r0 = (blockIdx.x * 8 + warp) * 2;
    if (r0 >= N_NODES) return;
    bool has1 = (r0 + 1 < N_NODES);

    int pA = g_ptr[r0], pB = g_ptr[r0 + 1];
    int pC = has1 ? g_ptr[r0 + 2] : pB;

    float a0 = 0.0f, a1 = 0.0f;
    float c0 = 0.0f, c1 = 0.0f;

    int len0 = pB - pA, len1 = pC - pB;
    int nmin = len0 < len1 ? len0 : len1;

#pragma unroll 2
    for (int i = 0; i < nmin; i++) {
        int2 e1 = g_edge[pA + i];
        int2 e2 = g_edge[pB + i];
        float v1 = __int_as_float(e1.y);
        float v2 = __int_as_float(e2.y);
        float2 h1 = __half22float2(g_h0h[(long)e1.x * 32 + lane]);
        float2 h2 = __half22float2(g_h0h[(long)e2.x * 32 + lane]);
        a0 += v1 * h1.x; a1 += v1 * h1.y;
        c0 += v2 * h2.x; c1 += v2 * h2.y;
    }
#pragma unroll 4
    for (int e = pA + nmin; e < pB; e++) {
        int2 ed = g_edge[e];
        float v = __int_as_float(ed.y);
        float2 h = __half22float2(g_h0h[(long)ed.x * 32 + lane]);
        a0 += v * h.x; a1 += v * h.y;
    }
#pragma unroll 4
    for (int e = pB + nmin; e < pC; e++) {
        int2 ed = g_edge[e];
        float v = __int_as_float(ed.y);
        float2 h = __half22float2(g_h0h[(long)ed.x * 32 + lane]);
        c0 += v * h.x; c1 += v * h.y;
    }

    g_hh[(long)r0 * 32 + lane] =
        __floats2half2_rn(fmaxf(a0, 0.0f), fmaxf(a1, 0.0f));
    if (has1)
        g_hh[(long)(r0 + 1) * 32 + lane] =
            __floats2half2_rn(fmaxf(c0, 0.0f), fmaxf(c1, 0.0f));
}

// ---------------------------------------------------------------------------
// Dense layer 2: h2[n][j] = h[n][:] @ W2[:,j] + b2[j] (proven R15).
// ---------------------------------------------------------------------------
__global__ __launch_bounds__(256) void k_gemm2s(const float* __restrict__ W2,
                                                const float* __restrict__ b2) {
    __shared__ float w2s[N_HID][17];
    __shared__ float sh[16][65];
    __shared__ float b2s[N_CLS];

    int tid = threadIdx.x;
    for (int i = tid; i < N_HID * N_CLS; i += 256)
        w2s[i >> 4][i & 15] = W2[i];
    if (tid < N_CLS) b2s[tid] = b2[tid];

    int n0 = blockIdx.x * 16;
    for (int i = tid; i < 512; i += 256) {
        int nl = i >> 5, l = i & 31;
        float2 hv = __half22float2(g_hh[(long)(n0 + nl) * 32 + l]);
        sh[nl][2 * l] = hv.x;
        sh[nl][2 * l + 1] = hv.y;
    }
    __syncthreads();

    int nl = tid >> 4, j = tid & 15;
    float acc = b2s[j];
#pragma unroll
    for (int k = 0; k < N_HID; k++)
        acc += sh[nl][k] * w2s[k][j];
    g_h2h[(long)(n0 + nl) * N_CLS + j] = __float2half(acc);
}

// ---------------------------------------------------------------------------
// SpMM2 fused with log_softmax: half-warp per row, unroll 4 (proven).
// ---------------------------------------------------------------------------
__global__ __launch_bounds__(256) void k_spmm2f(float* __restrict__ out) {
    int tid = threadIdx.x;
    int warp = tid >> 5, lane = tid & 31;
    int half = lane >> 4, l16 = lane & 15;
    int r = (blockIdx.x * 8 + warp) * 2 + half;
    if (r >= N_NODES) return;

    int beg = g_ptr[r], end = g_ptr[r + 1];
    float acc = 0.0f;
#pragma unroll 4
    for (int e = beg; e < end; e++) {
        int2 ed = g_edge[e];
        acc += __int_as_float(ed.y) *
               __half2float(g_h2h[(long)ed.x * N_CLS + l16]);
    }
    float m = acc;
#pragma unroll
    for (int off = 8; off; off >>= 1)
        m = fmaxf(m, __shfl_xor_sync(0xffffffffu, m, off, 16));
    float s = expf(acc - m);
#pragma unroll
    for (int off = 8; off; off >>= 1)
        s += __shfl_xor_sync(0xffffffffu, s, off, 16);
    out[(long)r * N_CLS + l16] = acc - m - logf(s);
}

// ---------------------------------------------------------------------------
extern "C" void kernel_launch(void* const* d_in, const int* in_sizes, int n_in,
                              void* d_out, int out_size) {
    const float* x     = (const float*)d_in[0];
    const int*   arow  = (const int*)  d_in[1];
    const int*   acol  = (const int*)  d_in[2];
    const float* avals = (const float*)d_in[3];
    const float* W1    = (const float*)d_in[4];
    const float* b1    = (const float*)d_in[5];
    const float* W2    = (const float*)d_in[6];
    const float* b2    = (const float*)d_in[7];
    float* out = (float*)d_out;

    void* cnt_ptr = nullptr;
    cudaGetSymbolAddress(&cnt_ptr, g_cnt);
    cudaMemsetAsync(cnt_ptr, 0, N_NODES * sizeof(int));

    k_hist<<<(N_EDGES / 4 + 255) / 256, 256>>>(arow);   // 1 (4 edges/thread)
    k_scan1<<<SCAN_NBLK, SCAN_BLK>>>();                 // 2
    k_scan3<<<SCAN_NBLK, SCAN_BLK>>>();                 // 3
    k_gemm1<<<(N_NODES + 127) / 128, 256>>>(x, W1, b1); // 4: profiled
    k_scatter<<<(N_EDGES / 4 + 255) / 256, 256>>>(arow, acol, avals); // 5
    k_spmm1g<<<(N_NODES + 15) / 16, 256>>>();           // 6: gather+relu
    k_gemm2s<<<N_NODES / 16, 256>>>(W2, b2);            // 7: dense layer 2
    k_spmm2f<<<(N_NODES + 15) / 16, 256>>>(out);        // 8
}

// round 17
// speedup vs baseline: 1.0778x; 1.0778x over previous
#include <cuda_runtime.h>
#include <cuda_fp16.h>

#define N_NODES 100000
#define N_EDGES 1600000
#define N_FEAT  256
#define N_HID   64
#define N_CLS   16

#define SCAN_BLK  512
#define SCAN_NBLK ((N_NODES + SCAN_BLK - 1) / SCAN_BLK)   // 196

// ---------------- scratch (device globals: allocation-free, graph-safe) ----
__device__ __half2 g_h0h[N_NODES * (N_HID / 2)];  // x@W1+b1, fp16 pairs
__device__ __half2 g_hh [N_NODES * (N_HID / 2)];  // relu(spmm1), fp16 pairs
__device__ __half  g_h2h[N_NODES * N_CLS];        // h@W2+b2, fp16
__device__ int     g_cnt[N_NODES];
__device__ int     g_scan[N_NODES];
__device__ int     g_blk[SCAN_NBLK];
__device__ int     g_ptr[N_NODES + 1];
__device__ int     g_cur[N_NODES];
__device__ int2    g_edge[N_EDGES];               // {col, float_bits(val)} by row

// ---------------------------------------------------------------------------
// CSR build (proven R15 scalar versions)
// ---------------------------------------------------------------------------
__global__ void k_hist(const int* __restrict__ row) {
    int e = blockIdx.x * blockDim.x + threadIdx.x;
    if (e < N_EDGES) atomicAdd(&g_cnt[row[e]], 1);
}

__global__ __launch_bounds__(SCAN_BLK) void k_scan1() {
    __shared__ int s[SCAN_BLK];
    int i = blockIdx.x * SCAN_BLK + threadIdx.x;
    int v = (i < N_NODES) ? g_cnt[i] : 0;
    s[threadIdx.x] = v;
    __syncthreads();
    for (int off = 1; off < SCAN_BLK; off <<= 1) {
        int t = (threadIdx.x >= off) ? s[threadIdx.x - off] : 0;
        __syncthreads();
        s[threadIdx.x] += t;
        __syncthreads();
    }
    if (i < N_NODES) g_scan[i] = s[threadIdx.x];
    if (threadIdx.x == SCAN_BLK - 1) g_blk[blockIdx.x] = s[threadIdx.x];
}

__global__ __launch_bounds__(SCAN_BLK) void k_scan3() {
    __shared__ int s[SCAN_BLK];
    int t = threadIdx.x;
    s[t] = (t < SCAN_NBLK && t < (int)blockIdx.x) ? g_blk[t] : 0;
    __syncthreads();
    for (int off = SCAN_BLK / 2; off; off >>= 1) {
        if (t < off) s[t] += s[t + off];
        __syncthreads();
    }
    int blkoff = s[0];
    int i = blockIdx.x * SCAN_BLK + t;
    if (i < N_NODES) {
        int excl = g_scan[i] - g_cnt[i] + blkoff;
        g_ptr[i] = excl;
        g_cur[i] = excl;
    }
    if (i == 0) g_ptr[N_NODES] = N_EDGES;
}

__global__ void k_scatter(const int* __restrict__ row, const int* __restrict__ col,
                          const float* __restrict__ vals) {
    int e = blockIdx.x * blockDim.x + threadIdx.x;
    if (e >= N_EDGES) return;
    int r = row[e];
    int pos = atomicAdd(&g_cur[r], 1);
    g_edge[pos] = make_int2(col[e], __float_as_int(vals[e]));
}

// ---------------------------------------------------------------------------
// mma + cp.async helpers
// ---------------------------------------------------------------------------
__device__ __forceinline__ void mma_tf32(float c[4], unsigned a0, unsigned a1,
                                         unsigned a2, unsigned a3,
                                         unsigned b0, unsigned b1) {
    asm("mma.sync.aligned.m16n8k8.row.col.f32.tf32.tf32.f32 "
        "{%0,%1,%2,%3}, {%4,%5,%6,%7}, {%8,%9}, {%0,%1,%2,%3};"
        : "+f"(c[0]), "+f"(c[1]), "+f"(c[2]), "+f"(c[3])
        : "r"(a0), "r"(a1), "r"(a2), "r"(a3), "r"(b0), "r"(b1));
}

__device__ __forceinline__ void cp16(unsigned* dst_smem, const void* src, bool pred) {
    unsigned saddr = (unsigned)__cvta_generic_to_shared(dst_smem);
    int sz = pred ? 16 : 0;
    asm volatile("cp.async.cg.shared.global [%0], [%1], 16, %2;\n"
                 :: "r"(saddr), "l"(src), "r"(sz));
}
__device__ __forceinline__ void cp_commit() {
    asm volatile("cp.async.commit_group;\n");
}
__device__ __forceinline__ void cp_wait_all() {
    asm volatile("cp.async.wait_group 0;\n");
}

// ---------------------------------------------------------------------------
// GEMM1 (tf32 tensor cores, cp.async 2-stage, KT=16) — proven R12 version.
// ---------------------------------------------------------------------------
__global__ __launch_bounds__(256) void k_gemm1(const float* __restrict__ x,
                                               const float* __restrict__ W1,
                                               const float* __restrict__ b1) {
    __shared__ unsigned xs[2][128][20];
    __shared__ unsigned ws[2][16][72];
    __shared__ float b1s[64];

    int tid = threadIdx.x;
    int n0 = blockIdx.x * 128;
    if (tid < 64) b1s[tid] = b1[tid];

    int warp = tid >> 5, lane = tid & 31;
    int qr = lane >> 2, qc = lane & 3;

    int xr = tid >> 1, xc = (tid & 1) * 8;
    long gn = n0 + xr;
    bool xok = (gn < N_NODES);
    const float* xsrc = x + (xok ? gn : 0) * N_FEAT + xc;
    int wk = tid >> 4, wc = (tid & 15) * 4;

    {
        unsigned* xd = &xs[0][xr][xc];
        cp16(xd, xsrc, xok);
        cp16(xd + 4, xsrc + 4, xok);
        cp16(&ws[0][wk][wc], W1 + (long)wk * N_HID + wc, true);
        cp_commit();
    }

    float c[8][4];
#pragma unroll
    for (int i = 0; i < 8; i++)
#pragma unroll
        for (int j = 0; j < 4; j++) c[i][j] = 0.0f;

    int m = warp * 16 + qr;

    const int NCHUNK = N_FEAT / 16;
    for (int ch = 0; ch < NCHUNK; ch++) {
        int cur = ch & 1;
        cp_wait_all();
        __syncthreads();

        if (ch + 1 < NCHUNK) {
            int k0 = (ch + 1) * 16;
            int nxt = cur ^ 1;
            unsigned* xd = &xs[nxt][xr][xc];
            cp16(xd, xsrc + k0, xok);
            cp16(xd + 4, xsrc + k0 + 4, xok);
            cp16(&ws[nxt][wk][wc], W1 + (long)(k0 + wk) * N_HID + wc, true);
            cp_commit();
        }

        const unsigned (*X)[20] = xs[cur];
        const unsigned (*W)[72] = ws[cur];
#pragma unroll
        for (int ks = 0; ks < 2; ks++) {
            int kq = ks * 8 + qc;
            unsigned a0 = X[m][kq];
            unsigned a1 = X[m + 8][kq];
            unsigned a2 = X[m][kq + 4];
            unsigned a3 = X[m + 8][kq + 4];
#pragma unroll
            for (int nt = 0; nt < 8; nt++) {
                unsigned b0 = W[kq][nt * 8 + qr];
                unsigned b1v = W[kq + 4][nt * 8 + qr];
                mma_tf32(c[nt], a0, a1, a2, a3, b0, b1v);
            }
        }
    }

    int row0 = n0 + warp * 16 + qr;
    int row1 = row0 + 8;
#pragma unroll
    for (int nt = 0; nt < 8; nt++) {
        int cc = nt * 8 + qc * 2;
        float bb0 = b1s[cc], bb1 = b1s[cc + 1];
        if (row0 < N_NODES)
            g_h0h[(long)row0 * 32 + (cc >> 1)] =
                __floats2half2_rn(c[nt][0] + bb0, c[nt][1] + bb1);
        if (row1 < N_NODES)
            g_h0h[(long)row1 * 32 + (cc >> 1)] =
                __floats2half2_rn(c[nt][2] + bb0, c[nt][3] + bb1);
    }
}

// ---------------------------------------------------------------------------
// SpMM1 gather + ReLU only (proven R15).
// ---------------------------------------------------------------------------
__global__ __launch_bounds__(256) void k_spmm1g() {
    int tid = threadIdx.x;
    int warp = tid >> 5, lane = tid & 31;
    int r0 = (blockIdx.x * 8 + warp) * 2;
    if (r0 >= N_NODES) return;
    bool has1 = (r0 + 1 < N_NODES);

    int pA = g_ptr[r0], pB = g_ptr[r0 + 1];
    int pC = has1 ? g_ptr[r0 + 2] : pB;

    float a0 = 0.0f, a1 = 0.0f;
    float c0 = 0.0f, c1 = 0.0f;

    int len0 = pB - pA, len1 = pC - pB;
    int nmin = len0 < len1 ? len0 : len1;

#pragma unroll 2
    for (int i = 0; i < nmin; i++) {
        int2 e1 = g_edge[pA + i];
        int2 e2 = g_edge[pB + i];
        float v1 = __int_as_float(e1.y);
        float v2 = __int_as_float(e2.y);
        float2 h1 = __half22float2(g_h0h[(long)e1.x * 32 + lane]);
        float2 h2 = __half22float2(g_h0h[(long)e2.x * 32 + lane]);
        a0 += v1 * h1.x; a1 += v1 * h1.y;
        c0 += v2 * h2.x; c1 += v2 * h2.y;
    }
#pragma unroll 4
    for (int e = pA + nmin; e < pB; e++) {
        int2 ed = g_edge[e];
        float v = __int_as_float(ed.y);
        float2 h = __half22float2(g_h0h[(long)ed.x * 32 + lane]);
        a0 += v * h.x; a1 += v * h.y;
    }
#pragma unroll 4
    for (int e = pB + nmin; e < pC; e++) {
        int2 ed = g_edge[e];
        float v = __int_as_float(ed.y);
        float2 h = __half22float2(g_h0h[(long)ed.x * 32 + lane]);
        c0 += v * h.x; c1 += v * h.y;
    }

    g_hh[(long)r0 * 32 + lane] =
        __floats2half2_rn(fmaxf(a0, 0.0f), fmaxf(a1, 0.0f));
    if (has1)
        g_hh[(long)(r0 + 1) * 32 + lane] =
            __floats2half2_rn(fmaxf(c0, 0.0f), fmaxf(c1, 0.0f));
}

// ---------------------------------------------------------------------------
// Dense layer 2 (proven R15).
// ---------------------------------------------------------------------------
__global__ __launch_bounds__(256) void k_gemm2s(const float* __restrict__ W2,
                                                const float* __restrict__ b2) {
    __shared__ float w2s[N_HID][17];
    __shared__ float sh[16][65];
    __shared__ float b2s[N_CLS];

    int tid = threadIdx.x;
    for (int i = tid; i < N_HID * N_CLS; i += 256)
        w2s[i >> 4][i & 15] = W2[i];
    if (tid < N_CLS) b2s[tid] = b2[tid];

    int n0 = blockIdx.x * 16;
    for (int i = tid; i < 512; i += 256) {
        int nl = i >> 5, l = i & 31;
        float2 hv = __half22float2(g_hh[(long)(n0 + nl) * 32 + l]);
        sh[nl][2 * l] = hv.x;
        sh[nl][2 * l + 1] = hv.y;
    }
    __syncthreads();

    int nl = tid >> 4, j = tid & 15;
    float acc = b2s[j];
#pragma unroll
    for (int k = 0; k < N_HID; k++)
        acc += sh[nl][k] * w2s[k][j];
    g_h2h[(long)(n0 + nl) * N_CLS + j] = __float2half(acc);
}

// ---------------------------------------------------------------------------
// SpMM2 fused with log_softmax (proven R15).
// ---------------------------------------------------------------------------
__global__ __launch_bounds__(256) void k_spmm2f(float* __restrict__ out) {
    int tid = threadIdx.x;
    int warp = tid >> 5, lane = tid & 31;
    int half = lane >> 4, l16 = lane & 15;
    int r = (blockIdx.x * 8 + warp) * 2 + half;
    if (r >= N_NODES) return;

    int beg = g_ptr[r], end = g_ptr[r + 1];
    float acc = 0.0f;
#pragma unroll 4
    for (int e = beg; e < end; e++) {
        int2 ed = g_edge[e];
        acc += __int_as_float(ed.y) *
               __half2float(g_h2h[(long)ed.x * N_CLS + l16]);
    }
    float m = acc;
#pragma unroll
    for (int off = 8; off; off >>= 1)
        m = fmaxf(m, __shfl_xor_sync(0xffffffffu, m, off, 16));
    float s = expf(acc - m);
#pragma unroll
    for (int off = 8; off; off >>= 1)
        s += __shfl_xor_sync(0xffffffffu, s, off, 16);
    out[(long)r * N_CLS + l16] = acc - m - logf(s);
}

// ---------------------------------------------------------------------------
extern "C" void kernel_launch(void* const* d_in, const int* in_sizes, int n_in,
                              void* d_out, int out_size) {
    const float* x     = (const float*)d_in[0];
    const int*   arow  = (const int*)  d_in[1];
    const int*   acol  = (const int*)  d_in[2];
    const float* avals = (const float*)d_in[3];
    const float* W1    = (const float*)d_in[4];
    const float* b1    = (const float*)d_in[5];
    const float* W2    = (const float*)d_in[6];
    const float* b2    = (const float*)d_in[7];
    float* out = (float*)d_out;

    // Second stream + fork/join events: created once on the (uncaptured)
    // correctness call, reused during graph capture. Multi-stream fork/join
    // via events is the documented capturable pattern.
    static cudaStream_t s2 = nullptr;
    static cudaEvent_t ev_fork = nullptr, ev_join = nullptr;
    if (s2 == nullptr) {
        cudaStreamCreateWithFlags(&s2, cudaStreamNonBlocking);
        cudaEventCreateWithFlags(&ev_fork, cudaEventDisableTiming);
        cudaEventCreateWithFlags(&ev_join, cudaEventDisableTiming);
    }

    void* cnt_ptr = nullptr;
    cudaGetSymbolAddress(&cnt_ptr, g_cnt);

    // fork: gemm1 runs on s2 concurrently with the CSR build chain
    cudaEventRecord(ev_fork, 0);
    cudaStreamWaitEvent(s2, ev_fork, 0);
    k_gemm1<<<(N_NODES + 127) / 128, 256, 0, s2>>>(x, W1, b1);
    cudaEventRecord(ev_join, s2);

    // CSR build chain on the capture (default) stream
    cudaMemsetAsync(cnt_ptr, 0, N_NODES * sizeof(int));
    k_hist<<<(N_EDGES + 255) / 256, 256>>>(arow);
    k_scan1<<<SCAN_NBLK, SCAN_BLK>>>();
    k_scan3<<<SCAN_NBLK, SCAN_BLK>>>();
    k_scatter<<<(N_EDGES + 255) / 256, 256>>>(arow, acol, avals);

    // join: spmm1g needs both gemm1 (g_h0h) and the CSR (g_ptr/g_edge)
    cudaStreamWaitEvent(0, ev_join, 0);
    k_spmm1g<<<(N_NODES + 15) / 16, 256>>>();
    k_gemm2s<<<N_NODES / 16, 256>>>(W2, b2);
    k_spmm2f<<<(N_NODES + 15) / 16, 256>>>(out);
}